// round 13
// baseline (speedup 1.0000x reference)
#include <cuda_runtime.h>

#define DTc 0.05f
typedef unsigned long long ull;

__device__ float g_s2  [64*256*64];
__device__ float g_xres[64*256*64];
__device__ float g_rx  [64*256*64];
__device__ float g_ru  [64*256*16];
__device__ float g_K   [64*256*16*64];
__device__ float g_kv  [64*256*16];
__device__ float g_s   [64*256*64];
__device__ float g_P   [(size_t)64*256*64*64];

#define XW_SZ (65*256*64)
#define UW_SZ (64*256*16)

__device__ __forceinline__ ull pack2(float x, float y) {
    ull r; asm("mov.b64 %0, {%1, %2};" : "=l"(r) : "f"(x), "f"(y)); return r;
}
__device__ __forceinline__ void unpack2(ull v, float& x, float& y) {
    asm("mov.b64 {%0, %1}, %2;" : "=f"(x), "=f"(y) : "l"(v));
}
__device__ __forceinline__ void ffma2(ull& d, ull a, ull b) {
    asm("fma.rn.f32x2 %0, %1, %2, %0;" : "+l"(d) : "l"(a), "l"(b));
}
__device__ __forceinline__ unsigned smem_u32(const void* p) {
    return (unsigned)__cvta_generic_to_shared(p);
}
__device__ __forceinline__ void cp16(unsigned saddr, const void* gaddr) {
    asm volatile("cp.async.ca.shared.global [%0], [%1], 16;" :: "r"(saddr), "l"(gaddr));
}
#define CP_COMMIT() asm volatile("cp.async.commit_group;")
#define CP_WAIT1()  asm volatile("cp.async.wait_group 1;")

__device__ __forceinline__ void tri_map(int t, int& R, int& C) {
    float f = sqrtf(8.f*(float)t + 1.f);
    R = (int)((f - 1.f) * 0.5f);
    C = t - ((R*(R+1)) >> 1);
    if (C > R) { R++; C = t - ((R*(R+1)) >> 1); }
    else if (C < 0) { R--; C = t - ((R*(R+1)) >> 1); }
}

// C(64x64) = A1 + alpha * (L K-col-scaled-by-s) @ R. 256 thr, 4x4 tiles, f32x2, ull2 R-loads.
__device__ __forceinline__ void gemm64f2(float* __restrict__ C,
    const float* __restrict__ L, const float* __restrict__ R,
    const float* __restrict__ s, float alpha, const float* __restrict__ A1)
{
    const int tid = threadIdx.x;
    const int c0 = (tid & 15) * 4, r0 = (tid >> 4) * 4;
    ull acc[4][2];
#pragma unroll
    for (int r = 0; r < 4; r++) { acc[r][0] = 0ull; acc[r][1] = 0ull; }
#pragma unroll 4
    for (int jj = 0; jj < 16; jj++) {
        float4 sv4 = *(const float4*)(s + jj*4);
        const float* sp = (const float*)&sv4;
        float4 lv[4]; ulonglong2 rv[4];
#pragma unroll
        for (int r = 0; r < 4; r++) lv[r] = *(const float4*)(L + (r0+r)*64 + jj*4);
#pragma unroll
        for (int q = 0; q < 4; q++) rv[q] = *(const ulonglong2*)(R + (jj*4+q)*64 + c0);
#pragma unroll
        for (int r = 0; r < 4; r++) {
            const float* lp = (const float*)&lv[r];
#pragma unroll
            for (int q = 0; q < 4; q++) {
                float m = lp[q]*sp[q];
                ull lb = pack2(m, m);
                ffma2(acc[r][0], lb, rv[q].x);
                ffma2(acc[r][1], lb, rv[q].y);
            }
        }
    }
#pragma unroll
    for (int r = 0; r < 4; r++) {
        float o[4];
        unpack2(acc[r][0], o[0], o[1]);
        unpack2(acc[r][1], o[2], o[3]);
        const int base = (r0+r)*64 + c0;
#pragma unroll
        for (int c = 0; c < 4; c++) C[base+c] = alpha*o[c] + A1[base+c];
    }
}

// C(64x16) = alpha * (L K-col-scaled-by-s)(64x64) @ R(64x16). 256 threads.
__device__ __forceinline__ void gemm6416f2(float* __restrict__ C,
    const float* __restrict__ L, const float* __restrict__ R,
    const float* __restrict__ s, float alpha)
{
    const int tid = threadIdx.x;
    const int c = tid & 15, r0 = (tid >> 4) * 4;
    ull acc01 = 0ull, acc23 = 0ull;
#pragma unroll 4
    for (int jj = 0; jj < 16; jj++) {
        float4 sv4 = *(const float4*)(s + jj*4);
        const float* sp = (const float*)&sv4;
        float4 lv[4];
#pragma unroll
        for (int r = 0; r < 4; r++) lv[r] = *(const float4*)(L + (r0+r)*64 + jj*4);
#pragma unroll
        for (int q = 0; q < 4; q++) {
            float rb = R[(jj*4+q)*16 + c];
            ull rbb = pack2(rb, rb);
            float f0 = ((const float*)&lv[0])[q]*sp[q], f1 = ((const float*)&lv[1])[q]*sp[q];
            float f2 = ((const float*)&lv[2])[q]*sp[q], f3 = ((const float*)&lv[3])[q]*sp[q];
            ffma2(acc01, pack2(f0, f1), rbb);
            ffma2(acc23, pack2(f2, f3), rbb);
        }
    }
    float o[4];
    unpack2(acc01, o[0], o[1]);
    unpack2(acc23, o[2], o[3]);
#pragma unroll
    for (int r = 0; r < 4; r++) C[(r0+r)*16 + c] = alpha * o[r];
}

// 4x4 tile of Qxx: C = QxG(global) + A2 + DT*(LT K-scaled) @ Rm; mirror if mir. ull2 R-loads.
__device__ __forceinline__ void qxx_tile(float* __restrict__ C,
    const float* __restrict__ LT, const float* __restrict__ Rm,
    const float* __restrict__ s, const float* __restrict__ QxG,
    const float* __restrict__ A2, int r0, int c0, bool mir)
{
    ull acc[4][2];
#pragma unroll
    for (int r = 0; r < 4; r++) { acc[r][0] = 0ull; acc[r][1] = 0ull; }
#pragma unroll 4
    for (int jj = 0; jj < 16; jj++) {
        float4 sv4 = *(const float4*)(s + jj*4);
        const float* sp = (const float*)&sv4;
        float4 lv[4]; ulonglong2 rv[4];
#pragma unroll
        for (int r = 0; r < 4; r++) lv[r] = *(const float4*)(LT + (r0+r)*64 + jj*4);
#pragma unroll
        for (int q = 0; q < 4; q++) rv[q] = *(const ulonglong2*)(Rm + (jj*4+q)*64 + c0);
#pragma unroll
        for (int r = 0; r < 4; r++) {
            const float* lp = (const float*)&lv[r];
#pragma unroll
            for (int q = 0; q < 4; q++) {
                float m = lp[q]*sp[q];
                ull lb = pack2(m, m);
                ffma2(acc[r][0], lb, rv[q].x);
                ffma2(acc[r][1], lb, rv[q].y);
            }
        }
    }
#pragma unroll
    for (int r = 0; r < 4; r++) {
        float o[4];
        unpack2(acc[r][0], o[0], o[1]);
        unpack2(acc[r][1], o[2], o[3]);
        const int base = (r0+r)*64 + c0;
        const float4 qv = __ldg((const float4*)(QxG + base));
        const float* qp = (const float*)&qv;
#pragma unroll
        for (int c = 0; c < 4; c++) {
            float v = DTc*o[c] + qp[c] + A2[base+c];
            C[base+c] = v;
            if (mir) C[(c0+c)*64 + (r0+r)] = v;
        }
    }
}

// 4x4 tile of Pn: C += L(64x16)@R(16x64); in place, mirror if mir. ull2 R-loads.
__device__ __forceinline__ void pn_tile(float* __restrict__ C,
    const float* __restrict__ L, const float* __restrict__ R,
    int r0, int c0, bool mir)
{
    ull acc[4][2];
#pragma unroll
    for (int r = 0; r < 4; r++) { acc[r][0] = 0ull; acc[r][1] = 0ull; }
#pragma unroll
    for (int jj = 0; jj < 4; jj++) {
        float4 lv[4]; ulonglong2 rv[4];
#pragma unroll
        for (int r = 0; r < 4; r++) lv[r] = *(const float4*)(L + (r0+r)*16 + jj*4);
#pragma unroll
        for (int q = 0; q < 4; q++) rv[q] = *(const ulonglong2*)(R + (jj*4+q)*64 + c0);
#pragma unroll
        for (int r = 0; r < 4; r++) {
            const float* lp = (const float*)&lv[r];
#pragma unroll
            for (int q = 0; q < 4; q++) {
                ull lb = pack2(lp[q], lp[q]);
                ffma2(acc[r][0], lb, rv[q].x);
                ffma2(acc[r][1], lb, rv[q].y);
            }
        }
    }
#pragma unroll
    for (int r = 0; r < 4; r++) {
        float o[4];
        unpack2(acc[r][0], o[0], o[1]);
        unpack2(acc[r][1], o[2], o[3]);
        const int base = (r0+r)*64 + c0;
#pragma unroll
        for (int c = 0; c < 4; c++) {
            float v = C[base+c] + o[c];
            C[base+c] = v;
            if (mir) C[(c0+c)*64 + (r0+r)] = v;
        }
    }
}

__global__ void init_kernel(const float* __restrict__ x_in, const float* __restrict__ u_in,
                            const float* __restrict__ lmd_in, float* __restrict__ out)
{
    int i = blockIdx.x * blockDim.x + threadIdx.x;
    if (i < XW_SZ) { out[i] = x_in[i]; out[XW_SZ + UW_SZ + i] = lmd_in[i]; }
    if (i < UW_SZ) out[XW_SZ + i] = u_in[i];
}

__global__ void __launch_bounds__(256) kkt_kernel(
    const float* __restrict__ A_in, const float* __restrict__ Bm_in,
    const float* __restrict__ Qx_in, const float* __restrict__ R_in,
    const float* __restrict__ xref_in, const float* __restrict__ out)
{
    extern __shared__ float ks[];
    float* kA   = ks;            float* kAT  = kA + 4096;
    float* kQx  = kAT + 4096;    float* kBm  = kQx + 4096;
    float* kBmT = kBm + 1024;    float* kR   = kBmT + 1024;
    float* sx   = kR + 256;      float* sxm  = sx + 256;
    float* sq   = sxm + 256;     float* su   = sq + 256;

    const int tid = threadIdx.x, b = blockIdx.x;
    for (int e = tid; e < 4096; e += 256) {
        float a = A_in[e];
        kA[e] = a;
        kAT[(e & 63)*64 + (e >> 6)] = a;
        kQx[e] = Qx_in[e];
    }
    for (int e = tid; e < 1024; e += 256) {
        float v = Bm_in[e];
        kBm[e] = v;
        kBmT[(e & 15)*64 + (e >> 4)] = v;
    }
    kR[tid] = R_in[tid];
    const int g = tid >> 6, j = tid & 63;
    const float xrefj = __ldg(xref_in + j);
    const float* xw = out;
    const float* uw = out + XW_SZ;
    const float* lw = uw + UW_SZ;
    float xnj, xn1j, l0j, l1j, uj = 0.f;
    {
        const int o0 = g*256 + b;
        xnj  = xw[o0*64 + j];  xn1j = xw[(o0+256)*64 + j];
        l0j  = lw[o0*64 + j];  l1j  = lw[(o0+256)*64 + j];
        if (j < 16) uj = uw[o0*16 + j];
    }
    __syncthreads();

    for (int t = 0; t < 16; t++) {
        const int n = t*4 + g;
        const int ofs = n*256 + b;
        sx[g*64 + j] = xnj;
        if (j < 16) su[g*16 + j] = uj;
        __syncthreads();
        float nx = 0.f, nx1 = 0.f, nl0 = 0.f, nl1 = 0.f, nu = 0.f;
        if (t < 15) {
            const int o2 = (n+4)*256 + b;
            nx  = xw[o2*64 + j];  nx1 = xw[(o2+256)*64 + j];
            nl0 = lw[o2*64 + j];  nl1 = lw[(o2+256)*64 + j];
            if (j < 16) nu = uw[o2*16 + j];
        }
        float z0 = 0.f, z1 = 0.f;
#pragma unroll 8
        for (int i = 0; i < 32; i++) {
            z0 = fmaf(kAT[i*64+j], sx[g*64+i], z0);
            z1 = fmaf(kAT[(i+32)*64+j], sx[g*64+i+32], z1);
        }
#pragma unroll
        for (int i = 0; i < 16; i++) z0 = fmaf(kBmT[i*64+j], su[g*16+i], z0);
        float z = z0 + z1;
        float tt = tanhf(z), s2 = 1.f - tt*tt;
        float xr = xnj + DTc*tt - xn1j;
        float q  = s2 * l1j;
        sq[g*64 + j]  = q;
        sxm[g*64 + j] = xnj - xrefj;
        __syncthreads();
        float a1 = 0.f, a2 = 0.f, a3 = 0.f, a4 = 0.f;
#pragma unroll 8
        for (int i = 0; i < 32; i++) {
            a1 = fmaf(kQx[i*64+j], sxm[g*64+i], a1);
            a2 = fmaf(kA[i*64+j],  sq[g*64+i],  a2);
            a3 = fmaf(kQx[(i+32)*64+j], sxm[g*64+i+32], a3);
            a4 = fmaf(kA[(i+32)*64+j],  sq[g*64+i+32],  a4);
        }
        g_s2[ofs*64+j]   = s2;
        g_xres[ofs*64+j] = xr;
        g_rx[ofs*64+j]   = (a1+a3) + l1j + DTc*(a2+a4) - l0j;
        if (j < 16) {
            float b1 = 0.f, b2 = 0.f;
#pragma unroll
            for (int i = 0; i < 16; i++) b1 = fmaf(kR[i*16+j], su[g*16+i], b1);
#pragma unroll 8
            for (int i = 0; i < 64; i++) b2 = fmaf(kBm[i*16+j], sq[g*64+i], b2);
            g_ru[ofs*16+j] = b1 + DTc*b2;
        }
        __syncthreads();
        xnj = nx; xn1j = nx1; l0j = nl0; l1j = nl1; uj = nu;
    }
}

__global__ void __launch_bounds__(256, 2) solve_kernel(
    const float* __restrict__ x0_in, const float* __restrict__ A_in,
    const float* __restrict__ Bm_in, const float* __restrict__ Qx_in,
    const float* __restrict__ R_in,  const float* __restrict__ Vf_in,
    const float* __restrict__ xref_in, float* __restrict__ out)
{
    extern __shared__ float sh[];
    float* sA   = sh;             // 4096 (fwd: P buf 0)
    float* sAT  = sA + 4096;      // 4096
    float* sP   = sAT + 4096;     // 4096
    float* sM1  = sP + 4096;      // 4096 (fwd: P buf 1)
    float* sBm  = sM1 + 4096;     // 1024
    float* sBmT = sBm + 1024;     // 1024
    float* sPFu = sBmT + 1024;    // 1024 (fwd: aux bufs 2x224)
    float* sQxu = sPFu + 1024;    // 1024 (fwd: K buf 0)
    float* sK   = sQxu + 1024;    // 1024 (fwd: K buf 1)
    float* sR   = sK + 1024;      // 256
    float* sQI  = sR + 256;       // 288
    float* vrN  = sQI + 288;      // 64
    float* vx0r = vrN + 64;       // 64
    float* vsv  = vx0r + 64;      // 64
    float* vv   = vsv + 64;       // 64
    float* vq2  = vv + 64;        // 64
    float* vlx  = vq2 + 64;       // 64
    float* vdx  = vlx + 64;       // 64
    float* vkk  = vdx + 64;       // 32
    float* vlu  = vkk + 32;       // 32
    float* vdu  = vlu + 32;       // 32
    float* sRed = vdu + 32;       // 256
    float* sRedB= sRed + 256;     // 256
    float* sRedC= sRedB + 256;    // 64
    float* vb   = sRedC + 64;     // 448

    const int tid = threadIdx.x, b = blockIdx.x;
    float* xw = out;
    float* uw = out + XW_SZ;
    float* lw = uw + UW_SZ;

    for (int e = tid; e < 4096; e += 256) {
        float a = A_in[e];
        sA[e] = a;
        sAT[(e & 63)*64 + (e >> 6)] = a;
    }
    for (int e = tid; e < 1024; e += 256) {
        float v = Bm_in[e];
        sBm[e] = v;
        sBmT[(e & 15)*64 + (e >> 4)] = v;
    }
    sR[tid] = R_in[tid];
    for (int e = tid; e < 4096; e += 256) sP[e] = Vf_in[e];
    if (tid < 64) {
        vv[tid]   = xw[(64*256 + b)*64 + tid] - __ldg(xref_in + tid);
        vx0r[tid] = xw[b*64 + tid] - x0_in[b*64 + tid];
    }
    __syncthreads();
    if (tid < 64) {
        const int j = tid; float a0 = 0.f, a1 = 0.f;
#pragma unroll 8
        for (int i = 0; i < 32; i++) {
            a0 = fmaf(sP[i*64+j], vv[i], a0);
            a1 = fmaf(sP[(i+32)*64+j], vv[i+32], a1);
        }
        float r = a0 + a1 - lw[(64*256 + b)*64 + j];
        vrN[j] = r; vsv[j] = r;
    }

    int TR, TC;
    tri_map(tid < 136 ? tid : 0, TR, TC);
    const int tr0 = TR*4, tc0 = TC*4;
    const bool tmir = (TR != TC);

    auto issue_bwd = [&](int n) {
        unsigned base = smem_u32(vb + (n&1)*224);
        size_t o64 = (size_t)(n*256 + b)*64;
        if (tid < 16)      cp16(base + tid*16,            g_rx   + o64 + tid*4);
        else if (tid < 32) cp16(base + 256 + (tid-16)*16, g_s2   + o64 + (tid-16)*4);
        else if (tid < 48) cp16(base + 512 + (tid-32)*16, g_xres + o64 + (tid-32)*4);
        else if (tid < 52) cp16(base + 768 + (tid-48)*16, g_ru + (size_t)(n*256+b)*16 + (tid-48)*4);
    };
    issue_bwd(63); CP_COMMIT();

    // ---------------- backward Riccati ----------------
    for (int n = 63; n >= 0; n--) {
        if (n > 0) issue_bwd(n-1);
        CP_COMMIT(); CP_WAIT1();
        __syncthreads();
        const float* rxb = vb + (n&1)*224;
        const float* s2b = rxb + 64;
        const float* xrb = rxb + 128;
        const float* rub = rxb + 192;
        const int ofs = n*256 + b;
        // D: spill P_{n+1}; PFx, PFu gemms; v/q2 matvec (2-acc)
        if (n < 63) {
            float4* gp = (float4*)(g_P + (size_t)(ofs+256)*4096);
            for (int e = tid; e < 1024; e += 256) gp[e] = ((const float4*)sP)[e];
        }
        gemm64f2(sM1, sP, sA, s2b, DTc, sP);
        gemm6416f2(sPFu, sP, sBm, s2b, DTc);
        if (tid >= 128 && tid < 192) {
            const int j = tid - 128; float a0 = 0.f, a1 = 0.f;
#pragma unroll 8
            for (int i = 0; i < 32; i++) {
                a0 = fmaf(sP[i*64+j], xrb[i], a0);
                a1 = fmaf(sP[(i+32)*64+j], xrb[i+32], a1);
            }
            float vv_ = a0 + a1 + vsv[j];
            vv[j] = vv_; vq2[j] = s2b[j] * vv_;
        }
        __syncthreads();
        // E: Qxx lower-tri -> sP (+mirror); Qxu; Quu
        if (tid < 136) {
            qxx_tile(sP, sAT, sM1, s2b, Qx_in, sM1, tr0, tc0, tmir);
        } else if (tid < 200) {
            const int t = tid - 136;
            const int c0 = (t & 3) * 4, r0 = (t >> 2) * 4;
            ull a01[4], a23[4];
#pragma unroll
            for (int r = 0; r < 4; r++) { a01[r] = 0ull; a23[r] = 0ull; }
#pragma unroll 4
            for (int jj = 0; jj < 16; jj++) {
                float4 sv4 = *(const float4*)(s2b + jj*4);
                const float* sp = (const float*)&sv4;
                float4 lv[4]; ulonglong2 rv[4];
#pragma unroll
                for (int r = 0; r < 4; r++) lv[r] = *(const float4*)(sAT + (r0+r)*64 + jj*4);
#pragma unroll
                for (int q = 0; q < 4; q++) rv[q] = *(const ulonglong2*)(sPFu + (jj*4+q)*16 + c0);
#pragma unroll
                for (int r = 0; r < 4; r++) {
                    const float* lp = (const float*)&lv[r];
#pragma unroll
                    for (int q = 0; q < 4; q++) {
                        float m = lp[q]*sp[q];
                        ull lb = pack2(m, m);
                        ffma2(a01[r], lb, rv[q].x);
                        ffma2(a23[r], lb, rv[q].y);
                    }
                }
            }
#pragma unroll
            for (int r = 0; r < 4; r++) {
                float o[4];
                unpack2(a01[r], o[0], o[1]);
                unpack2(a23[r], o[2], o[3]);
#pragma unroll
                for (int c = 0; c < 4; c++)
                    sQxu[(r0+r)*16 + c0+c] = sPFu[(r0+r)*16 + c0+c] + DTc*o[c];
            }
        } else if (tid < 232) {
            const int q = tid - 200;
            const int i = q >> 1, k0 = (q & 1) * 8;
            float acc[8] = {0,0,0,0,0,0,0,0};
#pragma unroll 8
            for (int j = 0; j < 64; j++) {
                float l = sBmT[i*64+j] * s2b[j];
#pragma unroll
                for (int k = 0; k < 8; k++)
                    acc[k] = fmaf(l, sPFu[j*16 + k0 + k], acc[k]);
            }
#pragma unroll
            for (int k = 0; k < 8; k++)
                sQI[i*17 + k0 + k] = sR[i*16 + k0 + k] + DTc*acc[k];
        }
        __syncthreads();
        // F: warp0 GJ inverse of Quu || lx (2-acc) || lu (2-acc)
        if (tid < 32) {
            const int lane = tid;
            float creg[16];
#pragma unroll
            for (int r = 0; r < 16; r++)
                creg[r] = (lane < 16) ? sQI[r*17 + lane] : ((r == lane-16) ? 1.f : 0.f);
#pragma unroll
            for (int p = 0; p < 16; p++) {
                float piv = __shfl_sync(0xffffffffu, creg[p], p);
                float newp = creg[p] * (1.0f / piv);
#pragma unroll
                for (int r = 0; r < 16; r++) {
                    if (r == p) continue;
                    float fac = __shfl_sync(0xffffffffu, creg[r], p);
                    creg[r] = fmaf(-fac, newp, creg[r]);
                }
                creg[p] = newp;
            }
            if (lane >= 16) {
#pragma unroll
                for (int r = 0; r < 16; r++) sQI[r*17 + (lane-16)] = creg[r];
            }
        } else if (tid >= 64 && tid < 128) {
            const int j = tid - 64; float a0 = 0.f, a1 = 0.f;
#pragma unroll 8
            for (int i = 0; i < 32; i++) {
                a0 = fmaf(sA[i*64+j], vq2[i], a0);
                a1 = fmaf(sA[(i+32)*64+j], vq2[i+32], a1);
            }
            vlx[j] = rxb[j] + vv[j] + DTc*(a0+a1);
        } else if (tid >= 128 && tid < 144) {
            const int j = tid - 128; float a0 = 0.f, a1 = 0.f;
#pragma unroll 8
            for (int i = 0; i < 32; i++) {
                a0 = fmaf(sBm[i*16+j], vq2[i], a0);
                a1 = fmaf(sBm[(i+32)*16+j], vq2[i+32], a1);
            }
            vlu[j] = rub[j] + DTc*(a0+a1);
        }
        __syncthreads();
        // G: K = -Inv @ Qxu^T (+g_K store); k = -Inv @ lu (+g_kv store)
        {
            const int i = tid & 15, m0 = (tid >> 4) * 4;
            float a0=0.f,a1=0.f,a2=0.f,a3=0.f;
#pragma unroll
            for (int j = 0; j < 16; j++) {
                const float iv = sQI[i*17+j];
                a0 = fmaf(iv, sQxu[(m0+0)*16+j], a0);
                a1 = fmaf(iv, sQxu[(m0+1)*16+j], a1);
                a2 = fmaf(iv, sQxu[(m0+2)*16+j], a2);
                a3 = fmaf(iv, sQxu[(m0+3)*16+j], a3);
            }
            sK[i*64+m0]=-a0; sK[i*64+m0+1]=-a1; sK[i*64+m0+2]=-a2; sK[i*64+m0+3]=-a3;
            ((float4*)(g_K + (size_t)ofs*1024))[i*16 + (m0>>2)] = make_float4(-a0,-a1,-a2,-a3);
        }
        if (tid < 16) {
            float a = 0.f;
#pragma unroll
            for (int j = 0; j < 16; j++) a = fmaf(sQI[tid*17+j], vlu[j], a);
            vkk[tid] = -a;
            g_kv[ofs*16 + tid] = -a;
        }
        __syncthreads();
        // H: Pn lower-tri in place (+mirror); sn (+g_s store)
        if (tid < 136) {
            pn_tile(sP, sQxu, sK, tr0, tc0, tmir);
        } else if (tid < 200) {
            const int j = tid - 136; float a = vlx[j];
#pragma unroll
            for (int s = 0; s < 16; s++) {
                int i = ((j>>1) + s) & 15;
                a = fmaf(sQxu[j*16+i], vkk[i], a);
            }
            vsv[j] = a; g_s[ofs*64+j] = a;
        }
    }
    __syncthreads();
    {
        float4* gp = (float4*)(g_P + (size_t)b*4096);
        for (int e = tid; e < 1024; e += 256) gp[e] = ((const float4*)sP)[e];
    }
    if (tid < 64) vdx[tid] = -vx0r[tid];
    __syncthreads();

    // ---------------- forward rollout (double-buffered cp.async, 2 barriers/step) ----------------
    float* pb[2] = { sA, sM1 };
    float* kb[2] = { sQxu, sK };
    float* ab    = sPFu;
    auto issue_fwd = [&](int n) {
        const int p = n & 1;
        const size_t o = (size_t)(n*256 + b);
        unsigned pbase = smem_u32(pb[p]);
        for (int t = tid; t < 1024; t += 256) cp16(pbase + t*16, g_P + o*4096 + t*4);
        unsigned kbase = smem_u32(kb[p]);
        cp16(kbase + tid*16, g_K + o*1024 + tid*4);
        unsigned abase = smem_u32(ab + p*224);
        if (tid < 16)      cp16(abase + tid*16,            g_s2   + o*64 + tid*4);
        else if (tid < 32) cp16(abase + 256 + (tid-16)*16, g_xres + o*64 + (tid-16)*4);
        else if (tid < 48) cp16(abase + 512 + (tid-32)*16, g_s    + o*64 + (tid-32)*4);
        else if (tid < 52) cp16(abase + 768 + (tid-48)*16, g_kv   + o*16 + (tid-48)*4);
    };
    issue_fwd(0); CP_COMMIT();
    for (int n = 0; n < 64; n++) {
        if (n < 63) issue_fwd(n+1);
        CP_COMMIT(); CP_WAIT1();
        __syncthreads();
        const float* P   = pb[n&1];
        const float* K   = kb[n&1];
        const float* aux = ab + (n&1)*224;
        const float* s2v = aux; const float* xrv = aux+64;
        const float* gsv = aux+128; const float* kvv = aux+192;
        const int ofs = n*256 + b;
        const int j = tid & 63, qt = tid >> 6;
        // ph1: aa/pp partials (all threads); K partials (tid<64)
        {
            float aa = 0.f, pp = 0.f;
#pragma unroll
            for (int s = 0; s < 16; s++) {
                int i = qt*16 + s;
                aa = fmaf(sAT[i*64+j], vdx[i], aa);
                pp = fmaf(P[i*64+j],   vdx[i], pp);
            }
            sRed[qt*64+j] = aa; sRedB[qt*64+j] = pp;
        }
        if (tid < 64) {
            const int ki = tid & 15, qs = tid >> 4;
            float a = 0.f;
#pragma unroll
            for (int s = 0; s < 16; s++) {
                int m = qs*16 + ((ki + s) & 15);
                a = fmaf(K[ki*64+m], vdx[m], a);
            }
            sRedC[qs*16+ki] = a;
        }
        __syncthreads();
        // ph2: finalize — du re-reduced locally (warp-broadcast sRedC reads)
        if (tid < 64) {
            float ax = sRed[j] + sRed[64+j] + sRed[128+j] + sRed[192+j];
            float px = sRedB[j] + sRedB[64+j] + sRedB[128+j] + sRedB[192+j];
            float bdu = 0.f;
#pragma unroll
            for (int i = 0; i < 16; i++) {
                float du_i = kvv[i] + sRedC[i] + sRedC[16+i] + sRedC[32+i] + sRedC[48+i];
                bdu = fmaf(sBmT[i*64+j], du_i, bdu);
            }
            float old = vdx[j];
            const int idx = ofs*64 + j;
            xw[idx] += old;
            lw[idx] += px + gsv[j];
            vdx[j] = old + DTc*s2v[j]*(ax + bdu) + xrv[j];
        } else if (tid < 80) {
            const int i = tid - 64;
            float du_i = kvv[i] + sRedC[i] + sRedC[16+i] + sRedC[32+i] + sRedC[48+i];
            uw[ofs*16 + i] += du_i;
        }
    }
    __syncthreads();
    if (tid < 64) {
        const int j = tid; float p0 = 0.f, p1 = 0.f;
#pragma unroll 8
        for (int i = 0; i < 32; i++) {
            p0 = fmaf(__ldg(Vf_in + i*64 + j), vdx[i], p0);
            p1 = fmaf(__ldg(Vf_in + (i+32)*64 + j), vdx[i+32], p1);
        }
        const int idx = (64*256 + b)*64 + j;
        xw[idx] += vdx[j];
        lw[idx] += p0 + p1 + vrN[j];
    }
}

extern "C" void kernel_launch(void* const* d_in, const int* in_sizes, int n_in,
                              void* d_out, int out_size) {
    const float* x0   = (const float*)d_in[0];
    const float* x    = (const float*)d_in[1];
    const float* u    = (const float*)d_in[2];
    const float* lmd  = (const float*)d_in[3];
    const float* A    = (const float*)d_in[4];
    const float* Bm   = (const float*)d_in[5];
    const float* Qx   = (const float*)d_in[6];
    const float* R    = (const float*)d_in[7];
    const float* Vf   = (const float*)d_in[8];
    const float* xref = (const float*)d_in[9];
    float* out = (float*)d_out;
    const int solve_smem = 94464;
    const int kkt_smem   = 65536;
    cudaFuncSetAttribute(solve_kernel, cudaFuncAttributeMaxDynamicSharedMemorySize, solve_smem);
    cudaFuncSetAttribute(kkt_kernel,   cudaFuncAttributeMaxDynamicSharedMemorySize, kkt_smem);
    init_kernel<<<4160, 256>>>(x, u, lmd, out);
    for (int it = 0; it < 2; it++) {
        kkt_kernel<<<256, 256, kkt_smem>>>(A, Bm, Qx, R, xref, out);
        solve_kernel<<<256, 256, solve_smem>>>(x0, A, Bm, Qx, R, Vf, xref, out);
    }
}

// round 15
// speedup vs baseline: 1.0563x; 1.0563x over previous
#include <cuda_runtime.h>

#define DTc 0.05f
typedef unsigned long long ull;

__device__ float g_s2  [64*256*64];
__device__ float g_xres[64*256*64];
__device__ float g_rx  [64*256*64];
__device__ float g_ru  [64*256*16];
__device__ float g_K   [64*256*16*64];
__device__ float g_kv  [64*256*16];
__device__ float g_s   [64*256*64];
__device__ float g_P   [(size_t)64*256*64*64];

#define XW_SZ (65*256*64)
#define UW_SZ (64*256*16)
#define SBT_S 68
#define PFT_S 68

__device__ __forceinline__ ull pack2(float x, float y) {
    ull r; asm("mov.b64 %0, {%1, %2};" : "=l"(r) : "f"(x), "f"(y)); return r;
}
__device__ __forceinline__ void unpack2(ull v, float& x, float& y) {
    asm("mov.b64 {%0, %1}, %2;" : "=f"(x), "=f"(y) : "l"(v));
}
__device__ __forceinline__ void ffma2(ull& d, ull a, ull b) {
    asm("fma.rn.f32x2 %0, %1, %2, %0;" : "+l"(d) : "l"(a), "l"(b));
}
__device__ __forceinline__ ull mulf2(ull a, ull b) {
    ull r; asm("mul.rn.f32x2 %0, %1, %2;" : "=l"(r) : "l"(a), "l"(b)); return r;
}
__device__ __forceinline__ float hsum2(ull v) { float x, y; unpack2(v, x, y); return x + y; }
__device__ __forceinline__ unsigned smem_u32(const void* p) {
    return (unsigned)__cvta_generic_to_shared(p);
}
__device__ __forceinline__ void cp16(unsigned saddr, const void* gaddr) {
    asm volatile("cp.async.ca.shared.global [%0], [%1], 16;" :: "r"(saddr), "l"(gaddr));
}
#define CP_COMMIT() asm volatile("cp.async.commit_group;")
#define CP_WAIT1()  asm volatile("cp.async.wait_group 1;")
// swizzled scalar index: row-major 64-stride, quad XOR
__device__ __forceinline__ int swz(int row, int col) {
    return row*64 + ((((col>>2) ^ ((row>>2)&7)))<<2) + (col&3);
}

__device__ __forceinline__ void tri_map(int t, int& R, int& C) {
    float f = sqrtf(8.f*(float)t + 1.f);
    R = (int)((f - 1.f) * 0.5f);
    C = t - ((R*(R+1)) >> 1);
    if (C > R) { R++; C = t - ((R*(R+1)) >> 1); }
    else if (C < 0) { R--; C = t - ((R*(R+1)) >> 1); }
}

__global__ void init_kernel(const float* __restrict__ x_in, const float* __restrict__ u_in,
                            const float* __restrict__ lmd_in, float* __restrict__ out)
{
    int i = blockIdx.x * blockDim.x + threadIdx.x;
    if (i < XW_SZ) { out[i] = x_in[i]; out[XW_SZ + UW_SZ + i] = lmd_in[i]; }
    if (i < UW_SZ) out[XW_SZ + i] = u_in[i];
}

__global__ void __launch_bounds__(256) kkt_kernel(
    const float* __restrict__ A_in, const float* __restrict__ Bm_in,
    const float* __restrict__ Qx_in, const float* __restrict__ R_in,
    const float* __restrict__ xref_in, const float* __restrict__ out)
{
    extern __shared__ float ks[];
    float* kA   = ks;            float* kAT  = kA + 4096;
    float* kQx  = kAT + 4096;    float* kBm  = kQx + 4096;
    float* kBmT = kBm + 1024;    float* kR   = kBmT + 1024;
    float* sx   = kR + 256;      float* sxm  = sx + 256;
    float* sq   = sxm + 256;     float* su   = sq + 256;

    const int tid = threadIdx.x, b = blockIdx.x;
    for (int e = tid; e < 4096; e += 256) {
        float a = A_in[e];
        kA[e] = a;
        kAT[(e & 63)*64 + (e >> 6)] = a;
        kQx[e] = Qx_in[e];
    }
    for (int e = tid; e < 1024; e += 256) {
        float v = Bm_in[e];
        kBm[e] = v;
        kBmT[(e & 15)*64 + (e >> 4)] = v;
    }
    kR[tid] = R_in[tid];
    const int g = tid >> 6, j = tid & 63;
    const float xrefj = __ldg(xref_in + j);
    const float* xw = out;
    const float* uw = out + XW_SZ;
    const float* lw = uw + UW_SZ;
    float xnj, xn1j, l0j, l1j, uj = 0.f;
    {
        const int o0 = g*256 + b;
        xnj  = xw[o0*64 + j];  xn1j = xw[(o0+256)*64 + j];
        l0j  = lw[o0*64 + j];  l1j  = lw[(o0+256)*64 + j];
        if (j < 16) uj = uw[o0*16 + j];
    }
    __syncthreads();

    for (int t = 0; t < 16; t++) {
        const int n = t*4 + g;
        const int ofs = n*256 + b;
        sx[g*64 + j] = xnj;
        if (j < 16) su[g*16 + j] = uj;
        __syncthreads();
        float nx = 0.f, nx1 = 0.f, nl0 = 0.f, nl1 = 0.f, nu = 0.f;
        if (t < 15) {
            const int o2 = (n+4)*256 + b;
            nx  = xw[o2*64 + j];  nx1 = xw[(o2+256)*64 + j];
            nl0 = lw[o2*64 + j];  nl1 = lw[(o2+256)*64 + j];
            if (j < 16) nu = uw[o2*16 + j];
        }
        float z0 = 0.f, z1 = 0.f;
#pragma unroll 8
        for (int i = 0; i < 32; i++) {
            z0 = fmaf(kAT[i*64+j], sx[g*64+i], z0);
            z1 = fmaf(kAT[(i+32)*64+j], sx[g*64+i+32], z1);
        }
#pragma unroll
        for (int i = 0; i < 16; i++) z0 = fmaf(kBmT[i*64+j], su[g*16+i], z0);
        float z = z0 + z1;
        float tt = tanhf(z), s2 = 1.f - tt*tt;
        float xr = xnj + DTc*tt - xn1j;
        float q  = s2 * l1j;
        sq[g*64 + j]  = q;
        sxm[g*64 + j] = xnj - xrefj;
        __syncthreads();
        float a1 = 0.f, a2 = 0.f, a3 = 0.f, a4 = 0.f;
#pragma unroll 8
        for (int i = 0; i < 32; i++) {
            a1 = fmaf(kQx[i*64+j], sxm[g*64+i], a1);
            a2 = fmaf(kA[i*64+j],  sq[g*64+i],  a2);
            a3 = fmaf(kQx[(i+32)*64+j], sxm[g*64+i+32], a3);
            a4 = fmaf(kA[(i+32)*64+j],  sq[g*64+i+32],  a4);
        }
        g_s2[ofs*64+j]   = s2;
        g_xres[ofs*64+j] = xr;
        g_rx[ofs*64+j]   = (a1+a3) + l1j + DTc*(a2+a4) - l0j;
        if (j < 16) {
            float b1 = 0.f, b2 = 0.f;
#pragma unroll
            for (int i = 0; i < 16; i++) b1 = fmaf(kR[i*16+j], su[g*16+i], b1);
#pragma unroll 8
            for (int i = 0; i < 64; i++) b2 = fmaf(kBm[i*16+j], sq[g*64+i], b2);
            g_ru[ofs*16+j] = b1 + DTc*b2;
        }
        __syncthreads();
        xnj = nx; xn1j = nx1; l0j = nl0; l1j = nl1; uj = nu;
    }
}

__global__ void __launch_bounds__(256, 2) solve_kernel(
    const float* __restrict__ x0_in, const float* __restrict__ A_in,
    const float* __restrict__ Bm_in, const float* __restrict__ Qx_in,
    const float* __restrict__ R_in,  const float* __restrict__ Vf_in,
    const float* __restrict__ xref_in, float* __restrict__ out)
{
    extern __shared__ float sh[];
    float* sA    = sh;              // 4096 flat A (fwd: P buf 0)
    float* sAT   = sA + 4096;       // 4096 swizzled A^T
    float* sP    = sAT + 4096;      // 4096 swizzled P
    float* sM1   = sP + 4096;       // 4096 swizzled M=PFx^T (fwd: P buf 1)
    float* sBm   = sM1 + 4096;      // 1024 flat Bm
    float* sBmT  = sBm + 1024;      // 16x68 Bm^T
    float* sPFuT = sBmT + 16*SBT_S; // 16x68 PFu^T (fwd: aux 2x224)
    float* sQxu  = sPFuT + 16*PFT_S;// 1024 flat 64x16 (fwd: K buf 0)
    float* sK    = sQxu + 1024;     // 1024 flat 16x64 (fwd: K buf 1)
    float* sR    = sK + 1024;       // 256
    float* sQI   = sR + 256;        // 288
    float* vrN   = sQI + 288;  float* vx0r = vrN + 64;  float* vsv = vx0r + 64;
    float* vv    = vsv + 64;   float* vq2  = vv + 64;   float* vlx = vq2 + 64;
    float* vdx   = vlx + 64;   float* vkk  = vdx + 64;  float* vlu = vkk + 16;
    float* vdu   = vlu + 16;
    float* sRed  = vdu + 16;   float* sRedB = sRed + 256; float* sRedC = sRedB + 256;
    float* vb    = sRedC + 64; // 448

    const int tid = threadIdx.x, b = blockIdx.x;
    float* xw = out;
    float* uw = out + XW_SZ;
    float* lw = uw + UW_SZ;

    for (int e = tid; e < 4096; e += 256) {
        float a = A_in[e];
        sA[e] = a;
        int i = e >> 6, j = e & 63;
        sAT[swz(j, i)] = a;             // AT[j][i] = A[i][j]
        sP[swz(i, j)] = Vf_in[e];       // P_N = Vf (swizzled)
    }
    for (int e = tid; e < 1024; e += 256) {
        float v = Bm_in[e];
        sBm[e] = v;
        sBmT[(e & 15)*SBT_S + (e >> 4)] = v;
    }
    sR[tid] = R_in[tid];
    if (tid < 64) {
        vv[tid]   = xw[(64*256 + b)*64 + tid] - __ldg(xref_in + tid);
        vx0r[tid] = xw[b*64 + tid] - x0_in[b*64 + tid];
    }
    __syncthreads();
    if (tid < 64) {
        const int j = tid, jq = j >> 2, jr = j & 3;
        float a0 = 0.f;
#pragma unroll 8
        for (int i = 0; i < 64; i++)
            a0 = fmaf(sP[i*64 + ((jq ^ ((i>>2)&7))<<2) + jr], vv[i], a0);
        float r = a0 - lw[(64*256 + b)*64 + j];
        vrN[j] = r; vsv[j] = r;
    }

    int TR, TC;
    tri_map(tid < 136 ? tid : 0, TR, TC);
    const int tr0 = TR*4, tc0 = TC*4;
    const bool tmir = (TR != TC);
    const int xr_t = (tr0 >> 2) & 7, xc_t = (tc0 >> 2) & 7;

    auto issue_bwd = [&](int n) {
        unsigned base = smem_u32(vb + (n&1)*224);
        size_t o64 = (size_t)(n*256 + b)*64;
        if (tid < 16)      cp16(base + tid*16,            g_rx   + o64 + tid*4);
        else if (tid < 32) cp16(base + 256 + (tid-16)*16, g_s2   + o64 + (tid-16)*4);
        else if (tid < 48) cp16(base + 512 + (tid-32)*16, g_xres + o64 + (tid-32)*4);
        else if (tid < 52) cp16(base + 768 + (tid-48)*16, g_ru + (size_t)(n*256+b)*16 + (tid-48)*4);
    };
    issue_bwd(63); CP_COMMIT();

    // ================= backward Riccati =================
    for (int n = 63; n >= 0; n--) {
        if (n > 0) issue_bwd(n-1);
        CP_COMMIT(); CP_WAIT1();
        __syncthreads();
        const float* rxb = vb + (n&1)*224;
        const float* s2b = rxb + 64;
        const float* xrb = rxb + 128;
        const float* rub = rxb + 192;
        const int ofs = n*256 + b;
        // ---- D: spill P (raw swizzled); M = PFx^T (k-split); PFuT (k-split); v/q2 ----
        if (n < 63) {
            float4* gp = (float4*)(g_P + (size_t)(ofs+256)*4096);
            for (int e = tid; e < 1024; e += 256) gp[e] = ((const float4*)sP)[e];
        }
        {   // M[r][c] = P[r][c] + DT * sum_k AT[r][k] s2[k] P[c][k]
            const int r0 = (tid >> 4) * 4, c0 = (tid & 15) * 4;
            const int xa = (r0 >> 2) & 7, xc = (c0 >> 2) & 7;
            ull acc[4][4];
#pragma unroll
            for (int r = 0; r < 4; r++) { acc[r][0]=0; acc[r][1]=0; acc[r][2]=0; acc[r][3]=0; }
#pragma unroll 4
            for (int k0 = 0; k0 < 64; k0 += 4) {
                const int q = k0 >> 2;
                const int qa4 = (q ^ xa) << 2, qc4 = (q ^ xc) << 2;
                ulonglong2 sv = *(const ulonglong2*)(s2b + k0);
                ulonglong2 pv[4], av[4];
#pragma unroll
                for (int c = 0; c < 4; c++) pv[c] = *(const ulonglong2*)(sP + (c0+c)*64 + qc4);
#pragma unroll
                for (int r = 0; r < 4; r++) av[r] = *(const ulonglong2*)(sAT + (r0+r)*64 + qa4);
#pragma unroll
                for (int r = 0; r < 4; r++) {
                    ull t0 = mulf2(av[r].x, sv.x), t1 = mulf2(av[r].y, sv.y);
#pragma unroll
                    for (int c = 0; c < 4; c++) {
                        ffma2(acc[r][c], t0, pv[c].x);
                        ffma2(acc[r][c], t1, pv[c].y);
                    }
                }
            }
#pragma unroll
            for (int r = 0; r < 4; r++) {
                const int off = (r0+r)*64 + (((c0>>2) ^ xa) << 2);
                float4 pv = *(const float4*)(sP + off);
                float4 o;
                o.x = pv.x + DTc*hsum2(acc[r][0]);
                o.y = pv.y + DTc*hsum2(acc[r][1]);
                o.z = pv.z + DTc*hsum2(acc[r][2]);
                o.w = pv.w + DTc*hsum2(acc[r][3]);
                *(float4*)(sM1 + off) = o;
            }
        }
        {   // PFuT[c][r] = DT * sum_k BmT[c][k] s2[k] P[r][k]
            const int c = tid & 15, r0 = (tid >> 4) * 4;
            const int xp = (r0 >> 2) & 7;
            ull acc[4] = {0,0,0,0};
#pragma unroll 4
            for (int k0 = 0; k0 < 64; k0 += 4) {
                const int qp4 = ((k0>>2) ^ xp) << 2;
                ulonglong2 sv = *(const ulonglong2*)(s2b + k0);
                ulonglong2 bv = *(const ulonglong2*)(sBmT + c*SBT_S + k0);
                ull t0 = mulf2(bv.x, sv.x), t1 = mulf2(bv.y, sv.y);
#pragma unroll
                for (int r = 0; r < 4; r++) {
                    ulonglong2 pv = *(const ulonglong2*)(sP + (r0+r)*64 + qp4);
                    ffma2(acc[r], t0, pv.x);
                    ffma2(acc[r], t1, pv.y);
                }
            }
            float4 o;
            o.x = DTc*hsum2(acc[0]); o.y = DTc*hsum2(acc[1]);
            o.z = DTc*hsum2(acc[2]); o.w = DTc*hsum2(acc[3]);
            *(float4*)(sPFuT + c*PFT_S + r0) = o;
        }
        if (tid >= 128 && tid < 192) {
            const int j = tid - 128, jq = j >> 2, jr = j & 3;
            float a0 = 0.f;
#pragma unroll 8
            for (int i = 0; i < 64; i++)
                a0 = fmaf(sP[i*64 + ((jq ^ ((i>>2)&7))<<2) + jr], xrb[i], a0);
            float vv_ = a0 + vsv[j];
            vv[j] = vv_; vq2[j] = s2b[j] * vv_;
        }
        __syncthreads();
        // ---- E: Qxx tri -> sP (k-split); Qxu (k-split); Quu (k-split) ----
        if (tid < 136) {
            ull acc[4][4];
#pragma unroll
            for (int r = 0; r < 4; r++) { acc[r][0]=0; acc[r][1]=0; acc[r][2]=0; acc[r][3]=0; }
#pragma unroll 4
            for (int k0 = 0; k0 < 64; k0 += 4) {
                const int q = k0 >> 2;
                const int qr4 = (q ^ xr_t) << 2, qc4 = (q ^ xc_t) << 2;
                ulonglong2 sv = *(const ulonglong2*)(s2b + k0);
                ulonglong2 mv[4], av[4];
#pragma unroll
                for (int c = 0; c < 4; c++) mv[c] = *(const ulonglong2*)(sM1 + (tc0+c)*64 + qc4);
#pragma unroll
                for (int r = 0; r < 4; r++) av[r] = *(const ulonglong2*)(sAT + (tr0+r)*64 + qr4);
#pragma unroll
                for (int r = 0; r < 4; r++) {
                    ull t0 = mulf2(av[r].x, sv.x), t1 = mulf2(av[r].y, sv.y);
#pragma unroll
                    for (int c = 0; c < 4; c++) {
                        ffma2(acc[r][c], t0, mv[c].x);
                        ffma2(acc[r][c], t1, mv[c].y);
                    }
                }
            }
            float4 madd[4];
            const int mq4 = ((tr0>>2) ^ xc_t) << 2;
#pragma unroll
            for (int c = 0; c < 4; c++) madd[c] = *(const float4*)(sM1 + (tc0+c)*64 + mq4);
            const int sq4 = ((tc0>>2) ^ xr_t) << 2;
#pragma unroll
            for (int r = 0; r < 4; r++) {
                const float4 qv = __ldg((const float4*)(Qx_in + (tr0+r)*64 + tc0));
                const float* qp = (const float*)&qv;
#pragma unroll
                for (int c = 0; c < 4; c++) {
                    float v = qp[c] + ((const float*)&madd[c])[r] + DTc*hsum2(acc[r][c]);
                    sP[(tr0+r)*64 + sq4 + c] = v;
                    if (tmir) sP[(tc0+c)*64 + mq4 + r] = v;
                }
            }
        } else if (tid < 200) {
            const int t = tid - 136;
            const int c0 = (t & 3) * 4, r0 = (t >> 2) * 4;
            const int xa = (r0 >> 2) & 7;
            ull acc[4][4];
#pragma unroll
            for (int r = 0; r < 4; r++) { acc[r][0]=0; acc[r][1]=0; acc[r][2]=0; acc[r][3]=0; }
#pragma unroll 4
            for (int k0 = 0; k0 < 64; k0 += 4) {
                const int qa4 = ((k0>>2) ^ xa) << 2;
                ulonglong2 sv = *(const ulonglong2*)(s2b + k0);
                ulonglong2 pv[4], av[4];
#pragma unroll
                for (int c = 0; c < 4; c++) pv[c] = *(const ulonglong2*)(sPFuT + (c0+c)*PFT_S + k0);
#pragma unroll
                for (int r = 0; r < 4; r++) av[r] = *(const ulonglong2*)(sAT + (r0+r)*64 + qa4);
#pragma unroll
                for (int r = 0; r < 4; r++) {
                    ull t0 = mulf2(av[r].x, sv.x), t1 = mulf2(av[r].y, sv.y);
#pragma unroll
                    for (int c = 0; c < 4; c++) {
                        ffma2(acc[r][c], t0, pv[c].x);
                        ffma2(acc[r][c], t1, pv[c].y);
                    }
                }
            }
            float4 padd[4];
#pragma unroll
            for (int c = 0; c < 4; c++) padd[c] = *(const float4*)(sPFuT + (c0+c)*PFT_S + r0);
#pragma unroll
            for (int r = 0; r < 4; r++)
#pragma unroll
                for (int c = 0; c < 4; c++)
                    sQxu[(r0+r)*16 + c0+c] = ((const float*)&padd[c])[r] + DTc*hsum2(acc[r][c]);
        } else if (tid < 232) {
            const int qq = tid - 200;
            const int i = qq >> 1, k0c = (qq & 1) * 8;
            ull acc[8];
#pragma unroll
            for (int k = 0; k < 8; k++) acc[k] = 0;
#pragma unroll 4
            for (int k0 = 0; k0 < 64; k0 += 4) {
                ulonglong2 sv = *(const ulonglong2*)(s2b + k0);
                ulonglong2 bv = *(const ulonglong2*)(sBmT + i*SBT_S + k0);
                ull t0 = mulf2(bv.x, sv.x), t1 = mulf2(bv.y, sv.y);
#pragma unroll
                for (int k = 0; k < 8; k++) {
                    ulonglong2 pv = *(const ulonglong2*)(sPFuT + (k0c+k)*PFT_S + k0);
                    ffma2(acc[k], t0, pv.x);
                    ffma2(acc[k], t1, pv.y);
                }
            }
#pragma unroll
            for (int k = 0; k < 8; k++)
                sQI[i*17 + k0c + k] = sR[i*16 + k0c + k] + DTc*hsum2(acc[k]);
        }
        __syncthreads();
        // ---- F: warp0 GJ inverse || lx || lu ----
        if (tid < 32) {
            const int lane = tid;
            float creg[16];
#pragma unroll
            for (int r = 0; r < 16; r++)
                creg[r] = (lane < 16) ? sQI[r*17 + lane] : ((r == lane-16) ? 1.f : 0.f);
#pragma unroll
            for (int p = 0; p < 16; p++) {
                float piv = __shfl_sync(0xffffffffu, creg[p], p);
                float newp = creg[p] * (1.0f / piv);
#pragma unroll
                for (int r = 0; r < 16; r++) {
                    if (r == p) continue;
                    float fac = __shfl_sync(0xffffffffu, creg[r], p);
                    creg[r] = fmaf(-fac, newp, creg[r]);
                }
                creg[p] = newp;
            }
            if (lane >= 16) {
#pragma unroll
                for (int r = 0; r < 16; r++) sQI[r*17 + (lane-16)] = creg[r];
            }
        } else if (tid >= 64 && tid < 128) {
            const int j = tid - 64; float a0 = 0.f;
#pragma unroll 8
            for (int i = 0; i < 64; i++) a0 = fmaf(sA[i*64+j], vq2[i], a0);
            vlx[j] = rxb[j] + vv[j] + DTc*a0;
        } else if (tid >= 128 && tid < 144) {
            const int j = tid - 128; float a0 = 0.f;
#pragma unroll 8
            for (int i = 0; i < 64; i++) a0 = fmaf(sBm[i*16+j], vq2[i], a0);
            vlu[j] = rub[j] + DTc*a0;
        }
        __syncthreads();
        // ---- G: K = -Inv @ Qxu^T (+g_K); k = -Inv @ lu (+g_kv) ----
        {
            const int i = tid & 15, m0 = (tid >> 4) * 4;
            float a0=0.f,a1=0.f,a2=0.f,a3=0.f;
#pragma unroll
            for (int j = 0; j < 16; j++) {
                const float iv = sQI[i*17+j];
                a0 = fmaf(iv, sQxu[(m0+0)*16+j], a0);
                a1 = fmaf(iv, sQxu[(m0+1)*16+j], a1);
                a2 = fmaf(iv, sQxu[(m0+2)*16+j], a2);
                a3 = fmaf(iv, sQxu[(m0+3)*16+j], a3);
            }
            sK[i*64+m0]=-a0; sK[i*64+m0+1]=-a1; sK[i*64+m0+2]=-a2; sK[i*64+m0+3]=-a3;
            ((float4*)(g_K + (size_t)ofs*1024))[i*16 + (m0>>2)] = make_float4(-a0,-a1,-a2,-a3);
        }
        if (tid < 16) {
            float a = 0.f;
#pragma unroll
            for (int j = 0; j < 16; j++) a = fmaf(sQI[tid*17+j], vlu[j], a);
            vkk[tid] = -a;
            g_kv[ofs*16 + tid] = -a;
        }
        __syncthreads();
        // ---- H: Pn tri in place (R12 style, swizzled sP); sn ----
        if (tid < 136) {
            ull acc[4][2];
#pragma unroll
            for (int r = 0; r < 4; r++) { acc[r][0] = 0ull; acc[r][1] = 0ull; }
#pragma unroll
            for (int jj = 0; jj < 4; jj++) {
                float4 lv[4]; ulonglong2 rv[4];
#pragma unroll
                for (int r = 0; r < 4; r++) lv[r] = *(const float4*)(sQxu + (tr0+r)*16 + jj*4);
#pragma unroll
                for (int q = 0; q < 4; q++) rv[q] = *(const ulonglong2*)(sK + (jj*4+q)*64 + tc0);
#pragma unroll
                for (int r = 0; r < 4; r++) {
                    const float* lp = (const float*)&lv[r];
#pragma unroll
                    for (int q = 0; q < 4; q++) {
                        ull lb = pack2(lp[q], lp[q]);
                        ffma2(acc[r][0], lb, rv[q].x);
                        ffma2(acc[r][1], lb, rv[q].y);
                    }
                }
            }
            const int sq4 = ((tc0>>2) ^ xr_t) << 2;
            const int mq4 = ((tr0>>2) ^ xc_t) << 2;
#pragma unroll
            for (int r = 0; r < 4; r++) {
                float o[4];
                unpack2(acc[r][0], o[0], o[1]);
                unpack2(acc[r][1], o[2], o[3]);
#pragma unroll
                for (int c = 0; c < 4; c++) {
                    const int idx = (tr0+r)*64 + sq4 + c;
                    float v = sP[idx] + o[c];
                    sP[idx] = v;
                    if (tmir) sP[(tc0+c)*64 + mq4 + r] = v;
                }
            }
        } else if (tid < 200) {
            const int j = tid - 136; float a = vlx[j];
#pragma unroll
            for (int s = 0; s < 16; s++) {
                int i = ((j>>1) + s) & 15;
                a = fmaf(sQxu[j*16+i], vkk[i], a);
            }
            vsv[j] = a; g_s[ofs*64+j] = a;
        }
    }
    __syncthreads();
    {
        float4* gp = (float4*)(g_P + (size_t)b*4096);
        for (int e = tid; e < 1024; e += 256) gp[e] = ((const float4*)sP)[e];
    }
    if (tid < 64) vdx[tid] = -vx0r[tid];
    __syncthreads();

    // ---------------- forward rollout (double-buffered cp.async) ----------------
    float* pb[2] = { sA, sM1 };
    float* kb[2] = { sQxu, sK };
    float* ab    = sPFuT;
    auto issue_fwd = [&](int n) {
        const int p = n & 1;
        const size_t o = (size_t)(n*256 + b);
        unsigned pbase = smem_u32(pb[p]);
        for (int t = tid; t < 1024; t += 256) cp16(pbase + t*16, g_P + o*4096 + t*4);
        unsigned kbase = smem_u32(kb[p]);
        cp16(kbase + tid*16, g_K + o*1024 + tid*4);
        unsigned abase = smem_u32(ab + p*224);
        if (tid < 16)      cp16(abase + tid*16,            g_s2   + o*64 + tid*4);
        else if (tid < 32) cp16(abase + 256 + (tid-16)*16, g_xres + o*64 + (tid-16)*4);
        else if (tid < 48) cp16(abase + 512 + (tid-32)*16, g_s    + o*64 + (tid-32)*4);
        else if (tid < 52) cp16(abase + 768 + (tid-48)*16, g_kv   + o*16 + (tid-48)*4);
    };
    issue_fwd(0); CP_COMMIT();
    for (int n = 0; n < 64; n++) {
        if (n < 63) issue_fwd(n+1);
        CP_COMMIT(); CP_WAIT1();
        __syncthreads();
        const float* P   = pb[n&1];          // swizzled P
        const float* K   = kb[n&1];
        const float* aux = ab + (n&1)*224;
        const float* s2v = aux; const float* xrv = aux+64;
        const float* gsv = aux+128; const float* kvv = aux+192;
        const int ofs = n*256 + b;
        const int j = tid & 63, qt = tid >> 6;
        const int jq = j >> 2, jr = j & 3;
        {
            float aa = 0.f, pp = 0.f;
#pragma unroll
            for (int s = 0; s < 16; s++) {
                const int i = qt*16 + s;
                const int off = i*64 + ((jq ^ ((i>>2)&7))<<2) + jr;
                aa = fmaf(sAT[off], vdx[i], aa);
                pp = fmaf(P[off],   vdx[i], pp);
            }
            sRed[qt*64+j] = aa; sRedB[qt*64+j] = pp;
        }
        if (tid < 64) {
            const int ki = tid & 15, qs = tid >> 4;
            float a = 0.f;
#pragma unroll
            for (int s = 0; s < 16; s++) {
                int m = qs*16 + ((ki + s) & 15);
                a = fmaf(K[ki*64+m], vdx[m], a);
            }
            sRedC[qs*16+ki] = a;
        }
        __syncthreads();
        if (tid < 64) {
            float ax = sRed[j] + sRed[64+j] + sRed[128+j] + sRed[192+j];
            float px = sRedB[j] + sRedB[64+j] + sRedB[128+j] + sRedB[192+j];
            float bdu = 0.f;
#pragma unroll
            for (int i = 0; i < 16; i++) {
                float du_i = kvv[i] + sRedC[i] + sRedC[16+i] + sRedC[32+i] + sRedC[48+i];
                bdu = fmaf(sBmT[i*SBT_S+j], du_i, bdu);
            }
            float old = vdx[j];
            const int idx = ofs*64 + j;
            xw[idx] += old;
            lw[idx] += px + gsv[j];
            vdx[j] = old + DTc*s2v[j]*(ax + bdu) + xrv[j];
        } else if (tid < 80) {
            const int i = tid - 64;
            float du_i = kvv[i] + sRedC[i] + sRedC[16+i] + sRedC[32+i] + sRedC[48+i];
            uw[ofs*16 + i] += du_i;
        }
    }
    __syncthreads();
    if (tid < 64) {
        const int j = tid; float p0 = 0.f;
#pragma unroll 8
        for (int i = 0; i < 64; i++) p0 = fmaf(__ldg(Vf_in + i*64 + j), vdx[i], p0);
        const int idx = (64*256 + b)*64 + j;
        xw[idx] += vdx[j];
        lw[idx] += p0 + vrN[j];
    }
}

extern "C" void kernel_launch(void* const* d_in, const int* in_sizes, int n_in,
                              void* d_out, int out_size) {
    const float* x0   = (const float*)d_in[0];
    const float* x    = (const float*)d_in[1];
    const float* u    = (const float*)d_in[2];
    const float* lmd  = (const float*)d_in[3];
    const float* A    = (const float*)d_in[4];
    const float* Bm   = (const float*)d_in[5];
    const float* Qx   = (const float*)d_in[6];
    const float* R    = (const float*)d_in[7];
    const float* Vf   = (const float*)d_in[8];
    const float* xref = (const float*)d_in[9];
    float* out = (float*)d_out;
    const int solve_smem = 96768;   // 23696 floats audited + pad
    const int kkt_smem   = 65536;
    cudaFuncSetAttribute(solve_kernel, cudaFuncAttributeMaxDynamicSharedMemorySize, solve_smem);
    cudaFuncSetAttribute(kkt_kernel,   cudaFuncAttributeMaxDynamicSharedMemorySize, kkt_smem);
    init_kernel<<<4160, 256>>>(x, u, lmd, out);
    for (int it = 0; it < 2; it++) {
        kkt_kernel<<<256, 256, kkt_smem>>>(A, Bm, Qx, R, xref, out);
        solve_kernel<<<256, 256, solve_smem>>>(x0, A, Bm, Qx, R, Vf, xref, out);
    }
}